// round 1
// baseline (speedup 1.0000x reference)
#include <cuda_runtime.h>
#include <math.h>

#define Bsz 256
#define Ssz 200
#define Dsz 256
#define Hsz 8
#define DHsz 32
#define BS (Bsz * Ssz)   // 51200 rows

// Scratch (device globals: allocation-free per harness rules). 6 x 52.4MB.
__device__ float g_img_n[BS * Dsz];
__device__ float g_title_n[BS * Dsz];
__device__ float g_keff[BS * Dsz];
__device__ float g_ctx[BS * Dsz];
__device__ float g_h1[BS * Dsz];
__device__ float g_h1n[BS * Dsz];

// ---------------------------------------------------------------------------
// LayerNorm (torch variant: unbiased var, eps added to std)
// one block per row, 256 threads = 1 element/thread
// ---------------------------------------------------------------------------
__global__ void __launch_bounds__(256) ln_kernel(
    const float* __restrict__ x, const float* __restrict__ ga,
    const float* __restrict__ gb, float* __restrict__ y) {
    __shared__ float sm[8];
    int row = blockIdx.x;
    int t = threadIdx.x;
    int w = t >> 5, lane = t & 31;
    size_t off = (size_t)row * Dsz + t;
    float v = x[off];

    // sum reduction
    float s = v;
#pragma unroll
    for (int o = 16; o; o >>= 1) s += __shfl_xor_sync(0xffffffffu, s, o);
    if (lane == 0) sm[w] = s;
    __syncthreads();
    if (w == 0) {
        float x8 = (lane < 8) ? sm[lane] : 0.f;
#pragma unroll
        for (int o = 4; o; o >>= 1) x8 += __shfl_xor_sync(0xffffffffu, x8, o);
        if (lane == 0) sm[0] = x8;
    }
    __syncthreads();
    float mean = sm[0] * (1.0f / Dsz);
    __syncthreads();

    float d = v - mean;
    float ss = d * d;
#pragma unroll
    for (int o = 16; o; o >>= 1) ss += __shfl_xor_sync(0xffffffffu, ss, o);
    if (lane == 0) sm[w] = ss;
    __syncthreads();
    if (w == 0) {
        float x8 = (lane < 8) ? sm[lane] : 0.f;
#pragma unroll
        for (int o = 4; o; o >>= 1) x8 += __shfl_xor_sync(0xffffffffu, x8, o);
        if (lane == 0) sm[0] = x8;
    }
    __syncthreads();
    float var = sm[0] * (1.0f / (Dsz - 1));
    float inv = 1.0f / (sqrtf(var) + 1e-6f);
    y[off] = ga[t] * d * inv + gb[t];
}

// ---------------------------------------------------------------------------
// GEMM: out[m,n] = sum_k A[m,k] * W[n,k] + bias[n]  (+ epilogue)
// EPI==0: out += add[m,n]           (residual add)
// EPI==2: z = sffn[m%S] * out; out = add[m,n] + gelu_tanh(z)
// 64x64 block tile, BK=16, 256 threads, 4x4 per thread.
// ---------------------------------------------------------------------------
template <int EPI>
__global__ void __launch_bounds__(256) gemm_kernel(
    const float* __restrict__ A, const float* __restrict__ W,
    const float* __restrict__ bias, const float* __restrict__ add,
    const float* __restrict__ sffn, float* __restrict__ out) {
    __shared__ float As[64][16];
    __shared__ float Bs[64][17];  // +1 pad: compute-read conflicts 16-way -> 2-way
    int m0 = blockIdx.y * 64;
    int n0 = blockIdx.x * 64;
    int tid = threadIdx.x;
    int tx = tid & 15, ty = tid >> 4;
    int lr = tid >> 2;         // 0..63
    int lc = (tid & 3) * 4;    // 0,4,8,12

    float acc[4][4] = {};

    for (int k0 = 0; k0 < Dsz; k0 += 16) {
        float4 av = *reinterpret_cast<const float4*>(A + (size_t)(m0 + lr) * Dsz + k0 + lc);
        float4 wv = *reinterpret_cast<const float4*>(W + (size_t)(n0 + lr) * Dsz + k0 + lc);
        As[lr][lc + 0] = av.x; As[lr][lc + 1] = av.y;
        As[lr][lc + 2] = av.z; As[lr][lc + 3] = av.w;
        Bs[lr][lc + 0] = wv.x; Bs[lr][lc + 1] = wv.y;
        Bs[lr][lc + 2] = wv.z; Bs[lr][lc + 3] = wv.w;
        __syncthreads();
#pragma unroll
        for (int k = 0; k < 16; k++) {
            float a[4], bv[4];
#pragma unroll
            for (int i = 0; i < 4; i++) a[i] = As[ty * 4 + i][k];
#pragma unroll
            for (int j = 0; j < 4; j++) bv[j] = Bs[tx * 4 + j][k];
#pragma unroll
            for (int i = 0; i < 4; i++)
#pragma unroll
                for (int j = 0; j < 4; j++)
                    acc[i][j] = fmaf(a[i], bv[j], acc[i][j]);
        }
        __syncthreads();
    }

#pragma unroll
    for (int i = 0; i < 4; i++) {
        int m = m0 + ty * 4 + i;
        int n = n0 + tx * 4;
        float4 bv = *reinterpret_cast<const float4*>(bias + n);
        float4 adv = *reinterpret_cast<const float4*>(add + (size_t)m * Dsz + n);
        float r[4] = {acc[i][0] + bv.x, acc[i][1] + bv.y,
                      acc[i][2] + bv.z, acc[i][3] + bv.w};
        float ad[4] = {adv.x, adv.y, adv.z, adv.w};
        if (EPI == 0) {
#pragma unroll
            for (int j = 0; j < 4; j++) r[j] += ad[j];
        } else {
            float sf = sffn[m % Ssz];
#pragma unroll
            for (int j = 0; j < 4; j++) {
                float z = sf * r[j];
                float th = tanhf(0.79788456080286536f * (z + 0.044715f * z * z * z));
                r[j] = ad[j] + 0.5f * z * (1.0f + th);
            }
        }
        float4 ov = make_float4(r[0], r[1], r[2], r[3]);
        *reinterpret_cast<float4*>(out + (size_t)m * Dsz + n) = ov;
    }
}

// ---------------------------------------------------------------------------
// Attention: one block per (b,h). K_eff and V resident in smem (stride 33:
// conflict-free for both [k][d]-scan and lane-per-d patterns).
// Each warp handles 25 queries as 5 passes of 5 (register-tiled scores).
// ---------------------------------------------------------------------------
__global__ void __launch_bounds__(256) attn_kernel(
    const float* __restrict__ img_n, const float* __restrict__ keff,
    const int* __restrict__ mask, const float* __restrict__ sattn,
    float* __restrict__ ctx) {
    extern __shared__ float smem[];
    float* K_s = smem;                     // 200*33
    float* V_s = K_s + Ssz * 33;           // 200*33
    float* q_s = V_s + Ssz * 33;           // 8*5*32
    float* p_s = q_s + 8 * 5 * 32;         // 8*5*200
    float* m_s = p_s + 8 * 5 * Ssz;        // 200 (1.0 = masked)

    int b = blockIdx.x >> 3;
    int h = blockIdx.x & 7;
    int tid = threadIdx.x;
    size_t base = ((size_t)b * Ssz) * Dsz + h * DHsz;

    for (int idx = tid; idx < Ssz * DHsz; idx += 256) {
        int s = idx >> 5, d = idx & 31;
        K_s[s * 33 + d] = keff[base + (size_t)s * Dsz + d];
        V_s[s * 33 + d] = img_n[base + (size_t)s * Dsz + d];
    }
    for (int k = tid; k < Ssz; k += 256)
        m_s[k] = (mask[b * Ssz + k] == 0) ? 1.f : 0.f;
    __syncthreads();

    int w = tid >> 5, lane = tid & 31;
    float* qw = q_s + w * 5 * 32;
    float* pw = p_s + w * 5 * Ssz;
    const float isq = 0.17677669529663687f;  // 1/sqrt(32)

    for (int pass = 0; pass < 5; pass++) {
        int q0 = w * 25 + pass * 5;
#pragma unroll
        for (int j = 0; j < 5; j++)
            qw[j * 32 + lane] = img_n[base + (size_t)(q0 + j) * Dsz + lane];
        __syncwarp();

        float acc[5][7];
#pragma unroll
        for (int j = 0; j < 5; j++)
#pragma unroll
            for (int i = 0; i < 7; i++) acc[j][i] = 0.f;

#pragma unroll
        for (int d = 0; d < 32; d++) {
            float kv[7];
#pragma unroll
            for (int i = 0; i < 7; i++) {
                int k = lane + 32 * i;
                if (k > Ssz - 1) k = Ssz - 1;  // clamped; result discarded
                kv[i] = K_s[k * 33 + d];
            }
#pragma unroll
            for (int j = 0; j < 5; j++) {
                float qv = qw[j * 32 + d];
#pragma unroll
                for (int i = 0; i < 7; i++)
                    acc[j][i] = fmaf(qv, kv[i], acc[j][i]);
            }
        }

#pragma unroll
        for (int j = 0; j < 5; j++) {
            float f = isq * sattn[h * Ssz + q0 + j];
            float vals[7];
            float mx = -3.0e38f;
#pragma unroll
            for (int i = 0; i < 7; i++) {
                int k = lane + 32 * i;
                float s = -3.0e38f;
                if (k < Ssz) {
                    s = acc[j][i] * f;
                    if (m_s[k] != 0.f) s = -1e9f;  // mask applied post-scale (matches ref)
                }
                vals[i] = s;
                mx = fmaxf(mx, s);
            }
#pragma unroll
            for (int o = 16; o; o >>= 1)
                mx = fmaxf(mx, __shfl_xor_sync(0xffffffffu, mx, o));
            float se = 0.f;
#pragma unroll
            for (int i = 0; i < 7; i++) {
                int k = lane + 32 * i;
                float e = (k < Ssz) ? __expf(vals[i] - mx) : 0.f;
                vals[i] = e;
                se += e;
            }
#pragma unroll
            for (int o = 16; o; o >>= 1)
                se += __shfl_xor_sync(0xffffffffu, se, o);
            float inv = 1.f / se;
#pragma unroll
            for (int i = 0; i < 7; i++) {
                int k = lane + 32 * i;
                if (k < Ssz) pw[j * Ssz + k] = vals[i] * inv;
            }
        }
        __syncwarp();

        // ctx: lane owns dim d = lane
        float c[5] = {0.f, 0.f, 0.f, 0.f, 0.f};
        for (int k = 0; k < Ssz; k++) {
            float v = V_s[k * 33 + lane];
#pragma unroll
            for (int j = 0; j < 5; j++)
                c[j] = fmaf(pw[j * Ssz + k], v, c[j]);
        }
#pragma unroll
        for (int j = 0; j < 5; j++)
            ctx[base + (size_t)(q0 + j) * Dsz + lane] = c[j];
        __syncwarp();
    }
}

// ---------------------------------------------------------------------------
extern "C" void kernel_launch(void* const* d_in, const int* in_sizes, int n_in,
                              void* d_out, int out_size) {
    const float* hidden_img   = (const float*)d_in[0];
    const float* hidden_title = (const float*)d_in[1];
    const int*   mask         = (const int*)  d_in[2];
    const float* a_img   = (const float*)d_in[3];
    const float* b_img   = (const float*)d_in[4];
    const float* a_title = (const float*)d_in[5];
    const float* b_title = (const float*)d_in[6];
    const float* Wb      = (const float*)d_in[7];
    const float* bb      = (const float*)d_in[8];
    const float* Wo      = (const float*)d_in[9];
    const float* bo      = (const float*)d_in[10];
    const float* sattn   = (const float*)d_in[11];
    const float* a_out   = (const float*)d_in[12];
    const float* b_out   = (const float*)d_in[13];
    const float* W1      = (const float*)d_in[14];
    const float* b1      = (const float*)d_in[15];
    const float* sffn    = (const float*)d_in[16];
    float* out = (float*)d_out;

    float *img_n, *title_n, *keff, *ctxb, *h1, *h1n;
    cudaGetSymbolAddress((void**)&img_n,   g_img_n);
    cudaGetSymbolAddress((void**)&title_n, g_title_n);
    cudaGetSymbolAddress((void**)&keff,    g_keff);
    cudaGetSymbolAddress((void**)&ctxb,    g_ctx);
    cudaGetSymbolAddress((void**)&h1,      g_h1);
    cudaGetSymbolAddress((void**)&h1n,     g_h1n);

    // 1) LayerNorms for both streams
    ln_kernel<<<BS, 256>>>(hidden_img, a_img, b_img, img_n);
    ln_kernel<<<BS, 256>>>(hidden_title, a_title, b_title, title_n);

    // 2) keff = title_n @ Wb^T + bb + img_n  (folds q.k + q.k_b into q.keff)
    dim3 gg(Dsz / 64, BS / 64);
    gemm_kernel<0><<<gg, 256>>>(title_n, Wb, bb, img_n, nullptr, keff);

    // 3) attention
    const int smem_bytes = (Ssz * 33 * 2 + 8 * 5 * 32 + 8 * 5 * Ssz + Ssz) * 4;
    cudaFuncSetAttribute(attn_kernel,
                         cudaFuncAttributeMaxDynamicSharedMemorySize, smem_bytes);
    attn_kernel<<<Bsz * Hsz, 256, smem_bytes>>>(img_n, keff, mask, sattn, ctxb);

    // 4) h1 = ctx @ Wo^T + bo + hidden_img
    gemm_kernel<0><<<gg, 256>>>(ctxb, Wo, bo, hidden_img, nullptr, h1);

    // 5) h1_n = LN(h1)
    ln_kernel<<<BS, 256>>>(h1, a_out, b_out, h1n);

    // 6) out = h1 + gelu_tanh(scale_ffn * (h1_n @ W1^T + b1))
    gemm_kernel<2><<<gg, 256>>>(h1n, W1, b1, h1, sffn, out);
}

// round 2
// speedup vs baseline: 1.2583x; 1.2583x over previous
#include <cuda_runtime.h>
#include <math.h>
#include <mma.h>

using namespace nvcuda;

#define Bsz 256
#define Ssz 200
#define Dsz 256
#define Hsz 8
#define DHsz 32
#define BS (Bsz * Ssz)   // 51200 rows

// Scratch (device globals: allocation-free per harness rules).
__device__ float g_img_n[BS * Dsz];
__device__ float g_title_n[BS * Dsz];
__device__ float g_keff[BS * Dsz];
__device__ float g_ctx[BS * Dsz];
__device__ float g_h1[BS * Dsz];
__device__ float g_h1n[BS * Dsz];

// ---------------------------------------------------------------------------
// LayerNorm (torch variant: unbiased var, eps added to std)
// ---------------------------------------------------------------------------
__global__ void __launch_bounds__(256) ln_kernel(
    const float* __restrict__ x, const float* __restrict__ ga,
    const float* __restrict__ gb, float* __restrict__ y) {
    __shared__ float sm[8];
    int row = blockIdx.x;
    int t = threadIdx.x;
    int w = t >> 5, lane = t & 31;
    size_t off = (size_t)row * Dsz + t;
    float v = x[off];

    float s = v;
#pragma unroll
    for (int o = 16; o; o >>= 1) s += __shfl_xor_sync(0xffffffffu, s, o);
    if (lane == 0) sm[w] = s;
    __syncthreads();
    if (w == 0) {
        float x8 = (lane < 8) ? sm[lane] : 0.f;
#pragma unroll
        for (int o = 4; o; o >>= 1) x8 += __shfl_xor_sync(0xffffffffu, x8, o);
        if (lane == 0) sm[0] = x8;
    }
    __syncthreads();
    float mean = sm[0] * (1.0f / Dsz);
    __syncthreads();

    float d = v - mean;
    float ss = d * d;
#pragma unroll
    for (int o = 16; o; o >>= 1) ss += __shfl_xor_sync(0xffffffffu, ss, o);
    if (lane == 0) sm[w] = ss;
    __syncthreads();
    if (w == 0) {
        float x8 = (lane < 8) ? sm[lane] : 0.f;
#pragma unroll
        for (int o = 4; o; o >>= 1) x8 += __shfl_xor_sync(0xffffffffu, x8, o);
        if (lane == 0) sm[0] = x8;
    }
    __syncthreads();
    float var = sm[0] * (1.0f / (Dsz - 1));
    float inv = 1.0f / (sqrtf(var) + 1e-6f);
    y[off] = ga[t] * d * inv + gb[t];
}

// ---------------------------------------------------------------------------
// TF32 tensor-core GEMM: out[m,n] = sum_k A[m,k]*W[n,k] + bias[n] (+ epilogue)
// EPI==0: out += add[m,n]
// EPI==2: z = sffn[m%S]*out; out = add[m,n] + gelu_tanh(z)
// 128x64 block tile, BK=32, 256 threads (8 warps as 4x2, each 32x32 via
// 2x2 wmma m16n16k8 tf32 fragments). Epilogue via smem C tile.
// ---------------------------------------------------------------------------
#define GBM 128
#define GBN 64
#define GBK 32
#define ASTR 40   // A/W smem row stride (floats); mult of 8 -> 32B aligned frag loads
#define CSTR 72   // C smem row stride

template <int EPI>
__global__ void __launch_bounds__(256) gemm_tf32(
    const float* __restrict__ A, const float* __restrict__ W,
    const float* __restrict__ bias, const float* __restrict__ add,
    const float* __restrict__ sffn, float* __restrict__ out) {
    __shared__ float sh[GBM * CSTR];           // 128*72*4 = 36864 B
    float* As = sh;                             // [128][40]
    float* Ws = sh + GBM * ASTR;                // [64][40]
    float* Cs = sh;                             // [128][72] (reused after k-loop)

    int m0 = blockIdx.y * GBM;
    int n0 = blockIdx.x * GBN;
    int tid = threadIdx.x;
    int wid = tid >> 5;
    int wm = wid >> 1;   // 0..3 -> rows wm*32
    int wn = wid & 1;    // 0..1 -> cols wn*32

    wmma::fragment<wmma::accumulator, 16, 16, 8, float> cf[2][2];
#pragma unroll
    for (int i = 0; i < 2; i++)
#pragma unroll
        for (int j = 0; j < 2; j++) wmma::fill_fragment(cf[i][j], 0.0f);

    for (int k0 = 0; k0 < Dsz; k0 += GBK) {
        // stage A tile: 128x32 = 1024 float4, 4 per thread
#pragma unroll
        for (int t = 0; t < 4; t++) {
            int idx = tid + 256 * t;
            int r = idx >> 3, c4 = (idx & 7) * 4;
            float4 v = *reinterpret_cast<const float4*>(
                A + (size_t)(m0 + r) * Dsz + k0 + c4);
            *reinterpret_cast<float4*>(As + r * ASTR + c4) = v;
        }
        // stage W tile: 64x32 = 512 float4, 2 per thread
#pragma unroll
        for (int t = 0; t < 2; t++) {
            int idx = tid + 256 * t;
            int r = idx >> 3, c4 = (idx & 7) * 4;
            float4 v = *reinterpret_cast<const float4*>(
                W + (size_t)(n0 + r) * Dsz + k0 + c4);
            *reinterpret_cast<float4*>(Ws + r * ASTR + c4) = v;
        }
        __syncthreads();

#pragma unroll
        for (int kk = 0; kk < GBK; kk += 8) {
            wmma::fragment<wmma::matrix_a, 16, 16, 8, wmma::precision::tf32,
                           wmma::row_major> af[2];
            wmma::fragment<wmma::matrix_b, 16, 16, 8, wmma::precision::tf32,
                           wmma::col_major> bf[2];
#pragma unroll
            for (int i = 0; i < 2; i++) {
                wmma::load_matrix_sync(af[i],
                    As + (wm * 32 + i * 16) * ASTR + kk, ASTR);
#pragma unroll
                for (int e = 0; e < af[i].num_elements; e++)
                    af[i].x[e] = wmma::__float_to_tf32(af[i].x[e]);
            }
#pragma unroll
            for (int j = 0; j < 2; j++) {
                wmma::load_matrix_sync(bf[j],
                    Ws + (wn * 32 + j * 16) * ASTR + kk, ASTR);
#pragma unroll
                for (int e = 0; e < bf[j].num_elements; e++)
                    bf[j].x[e] = wmma::__float_to_tf32(bf[j].x[e]);
            }
#pragma unroll
            for (int i = 0; i < 2; i++)
#pragma unroll
                for (int j = 0; j < 2; j++)
                    wmma::mma_sync(cf[i][j], af[i], bf[j], cf[i][j]);
        }
        __syncthreads();
    }

    // dump accumulators to smem C tile
#pragma unroll
    for (int i = 0; i < 2; i++)
#pragma unroll
        for (int j = 0; j < 2; j++)
            wmma::store_matrix_sync(
                Cs + (wm * 32 + i * 16) * CSTR + wn * 32 + j * 16,
                cf[i][j], CSTR, wmma::mem_row_major);
    __syncthreads();

    // epilogue: 128x64 = 2048 float4, 8 per thread
#pragma unroll
    for (int t = 0; t < 8; t++) {
        int idx = tid + 256 * t;
        int r = idx >> 4, c4 = (idx & 15) * 4;
        int m = m0 + r, n = n0 + c4;
        float4 cv = *reinterpret_cast<float4*>(Cs + r * CSTR + c4);
        float4 bv = *reinterpret_cast<const float4*>(bias + n);
        float4 adv = *reinterpret_cast<const float4*>(add + (size_t)m * Dsz + n);
        float rr[4] = {cv.x + bv.x, cv.y + bv.y, cv.z + bv.z, cv.w + bv.w};
        float ad[4] = {adv.x, adv.y, adv.z, adv.w};
        if (EPI == 0) {
#pragma unroll
            for (int j = 0; j < 4; j++) rr[j] += ad[j];
        } else {
            float sf = sffn[m % Ssz];
#pragma unroll
            for (int j = 0; j < 4; j++) {
                float z = sf * rr[j];
                float th = tanhf(0.79788456080286536f * (z + 0.044715f * z * z * z));
                rr[j] = ad[j] + 0.5f * z * (1.0f + th);
            }
        }
        *reinterpret_cast<float4*>(out + (size_t)m * Dsz + n) =
            make_float4(rr[0], rr[1], rr[2], rr[3]);
    }
}

// ---------------------------------------------------------------------------
// Attention: one block per (b,h). K stride 36 (float4-aligned, conflict-free
// both access patterns). Score pass float4-vectorized over d; P.V pass
// float4-vectorized over k (broadcast prob reads): ~2x fewer LDS cycles.
// ---------------------------------------------------------------------------
#define KSTR 36

__global__ void __launch_bounds__(256) attn_kernel(
    const float* __restrict__ img_n, const float* __restrict__ keff,
    const int* __restrict__ mask, const float* __restrict__ sattn,
    float* __restrict__ ctx) {
    extern __shared__ float smem[];
    float* K_s = smem;                       // 200*36
    float* V_s = K_s + Ssz * KSTR;           // 200*36
    float* q_s = V_s + Ssz * KSTR;           // 8*5*32
    float* p_s = q_s + 8 * 5 * 32;           // 8*5*200
    float* m_s = p_s + 8 * 5 * Ssz;          // 200 (1.0 = masked)

    int b = blockIdx.x >> 3;
    int h = blockIdx.x & 7;
    int tid = threadIdx.x;
    size_t base = ((size_t)b * Ssz) * Dsz + h * DHsz;

    for (int idx = tid; idx < Ssz * DHsz; idx += 256) {
        int s = idx >> 5, d = idx & 31;
        K_s[s * KSTR + d] = keff[base + (size_t)s * Dsz + d];
        V_s[s * KSTR + d] = img_n[base + (size_t)s * Dsz + d];
    }
    for (int k = tid; k < Ssz; k += 256)
        m_s[k] = (mask[b * Ssz + k] == 0) ? 1.f : 0.f;
    __syncthreads();

    int w = tid >> 5, lane = tid & 31;
    float* qw = q_s + w * 5 * 32;
    float* pw = p_s + w * 5 * Ssz;
    const float isq = 0.17677669529663687f;  // 1/sqrt(32)

    for (int pass = 0; pass < 5; pass++) {
        int q0 = w * 25 + pass * 5;
#pragma unroll
        for (int j = 0; j < 5; j++)
            qw[j * 32 + lane] = img_n[base + (size_t)(q0 + j) * Dsz + lane];
        __syncwarp();

        float acc[5][7];
#pragma unroll
        for (int j = 0; j < 5; j++)
#pragma unroll
            for (int i = 0; i < 7; i++) acc[j][i] = 0.f;

#pragma unroll
        for (int d4 = 0; d4 < 32; d4 += 4) {
            float4 q4[5];
#pragma unroll
            for (int j = 0; j < 5; j++)
                q4[j] = *reinterpret_cast<const float4*>(qw + j * 32 + d4);
#pragma unroll
            for (int i = 0; i < 7; i++) {
                int k = lane + 32 * i;
                if (k > Ssz - 1) k = Ssz - 1;  // clamped; result discarded
                float4 kv = *reinterpret_cast<const float4*>(K_s + k * KSTR + d4);
#pragma unroll
                for (int j = 0; j < 5; j++) {
                    acc[j][i] = fmaf(q4[j].x, kv.x, acc[j][i]);
                    acc[j][i] = fmaf(q4[j].y, kv.y, acc[j][i]);
                    acc[j][i] = fmaf(q4[j].z, kv.z, acc[j][i]);
                    acc[j][i] = fmaf(q4[j].w, kv.w, acc[j][i]);
                }
            }
        }

#pragma unroll
        for (int j = 0; j < 5; j++) {
            float f = isq * sattn[h * Ssz + q0 + j];
            float vals[7];
            float mx = -3.0e38f;
#pragma unroll
            for (int i = 0; i < 7; i++) {
                int k = lane + 32 * i;
                float s = -3.0e38f;
                if (k < Ssz) {
                    s = acc[j][i] * f;
                    if (m_s[k] != 0.f) s = -1e9f;
                }
                vals[i] = s;
                mx = fmaxf(mx, s);
            }
#pragma unroll
            for (int o = 16; o; o >>= 1)
                mx = fmaxf(mx, __shfl_xor_sync(0xffffffffu, mx, o));
            float se = 0.f;
#pragma unroll
            for (int i = 0; i < 7; i++) {
                int k = lane + 32 * i;
                float e = (k < Ssz) ? __expf(vals[i] - mx) : 0.f;
                vals[i] = e;
                se += e;
            }
#pragma unroll
            for (int o = 16; o; o >>= 1)
                se += __shfl_xor_sync(0xffffffffu, se, o);
            float inv = 1.f / se;
#pragma unroll
            for (int i = 0; i < 7; i++) {
                int k = lane + 32 * i;
                if (k < Ssz) pw[j * Ssz + k] = vals[i] * inv;
            }
        }
        __syncwarp();

        // ctx: lane owns dim d = lane; float4 over k
        float c[5] = {0.f, 0.f, 0.f, 0.f, 0.f};
        for (int k4 = 0; k4 < Ssz; k4 += 4) {
            float4 p4[5];
#pragma unroll
            for (int j = 0; j < 5; j++)
                p4[j] = *reinterpret_cast<const float4*>(pw + j * Ssz + k4);
            float v0 = V_s[(k4 + 0) * KSTR + lane];
            float v1 = V_s[(k4 + 1) * KSTR + lane];
            float v2 = V_s[(k4 + 2) * KSTR + lane];
            float v3 = V_s[(k4 + 3) * KSTR + lane];
#pragma unroll
            for (int j = 0; j < 5; j++) {
                c[j] = fmaf(p4[j].x, v0, c[j]);
                c[j] = fmaf(p4[j].y, v1, c[j]);
                c[j] = fmaf(p4[j].z, v2, c[j]);
                c[j] = fmaf(p4[j].w, v3, c[j]);
            }
        }
#pragma unroll
        for (int j = 0; j < 5; j++)
            ctx[base + (size_t)(q0 + j) * Dsz + lane] = c[j];
        __syncwarp();
    }
}

// ---------------------------------------------------------------------------
extern "C" void kernel_launch(void* const* d_in, const int* in_sizes, int n_in,
                              void* d_out, int out_size) {
    const float* hidden_img   = (const float*)d_in[0];
    const float* hidden_title = (const float*)d_in[1];
    const int*   mask         = (const int*)  d_in[2];
    const float* a_img   = (const float*)d_in[3];
    const float* b_img   = (const float*)d_in[4];
    const float* a_title = (const float*)d_in[5];
    const float* b_title = (const float*)d_in[6];
    const float* Wb      = (const float*)d_in[7];
    const float* bb      = (const float*)d_in[8];
    const float* Wo      = (const float*)d_in[9];
    const float* bo      = (const float*)d_in[10];
    const float* sattn   = (const float*)d_in[11];
    const float* a_out   = (const float*)d_in[12];
    const float* b_out   = (const float*)d_in[13];
    const float* W1      = (const float*)d_in[14];
    const float* b1      = (const float*)d_in[15];
    const float* sffn    = (const float*)d_in[16];
    float* out = (float*)d_out;

    float *img_n, *title_n, *keff, *ctxb, *h1, *h1n;
    cudaGetSymbolAddress((void**)&img_n,   g_img_n);
    cudaGetSymbolAddress((void**)&title_n, g_title_n);
    cudaGetSymbolAddress((void**)&keff,    g_keff);
    cudaGetSymbolAddress((void**)&ctxb,    g_ctx);
    cudaGetSymbolAddress((void**)&h1,      g_h1);
    cudaGetSymbolAddress((void**)&h1n,     g_h1n);

    // 1) LayerNorms for both streams
    ln_kernel<<<BS, 256>>>(hidden_img, a_img, b_img, img_n);
    ln_kernel<<<BS, 256>>>(hidden_title, a_title, b_title, title_n);

    // 2) keff = title_n @ Wb^T + bb + img_n  (folds q.k + q.k_b into q.keff)
    dim3 gg(Dsz / GBN, BS / GBM);
    gemm_tf32<0><<<gg, 256>>>(title_n, Wb, bb, img_n, nullptr, keff);

    // 3) attention
    const int smem_bytes = (Ssz * KSTR * 2 + 8 * 5 * 32 + 8 * 5 * Ssz + Ssz) * 4;
    cudaFuncSetAttribute(attn_kernel,
                         cudaFuncAttributeMaxDynamicSharedMemorySize, smem_bytes);
    attn_kernel<<<Bsz * Hsz, 256, smem_bytes>>>(img_n, keff, mask, sattn, ctxb);

    // 4) h1 = ctx @ Wo^T + bo + hidden_img
    gemm_tf32<0><<<gg, 256>>>(ctxb, Wo, bo, hidden_img, nullptr, h1);

    // 5) h1_n = LN(h1)
    ln_kernel<<<BS, 256>>>(h1, a_out, b_out, h1n);

    // 6) out = h1 + gelu_tanh(scale_ffn * (h1_n @ W1^T + b1))
    gemm_tf32<2><<<gg, 256>>>(h1n, W1, b1, h1, sffn, out);
}